// round 2
// baseline (speedup 1.0000x reference)
#include <cuda_runtime.h>
#include <cstddef>

#define Bn 8
#define Cn 4
#define Hn 768
#define Wn 768
#define Rr 8
#define NCH 19
#define EPSc 1e-4f
#define PADW 800
#define POFF 9

// scratch (static __device__ arrays: allocation-free per harness rules)
__device__ float g_hsum[(size_t)Bn * NCH * Hn * Wn];   // horizontal box sums of 19 product channels
__device__ float g_Ab [(size_t)2 * Bn * Hn * Wn];      // Asum, b
__device__ float g_hAb[(size_t)2 * Bn * Hn * Wn];      // horizontal box of Asum, b

// channel -> (planeA, planeB) product table; plane 4 = p, planes 0..3 = I_c, B=-1 -> identity
__constant__ int c_chA[NCH] = {0,1,2,3, 4, 4,4,4,4, 0,0,0,0,1,1,1,2,2,3};
__constant__ int c_chB[NCH] = {-1,-1,-1,-1, -1, 0,1,2,3, 0,1,2,3,1,2,3,2,3,3};

__device__ __forceinline__ int wcnt(int t, int L) {
    int lo = t - Rr; if (lo < 0) lo = 0;
    int hi = t + Rr; if (hi > L - 1) hi = L - 1;
    return hi - lo + 1;
}

// ---------------------------------------------------------------------------
// K1: per (b, y) row -> horizontal 17-tap box sums of 19 product channels.
// 608 threads = 19 channels x 32 segments of 24 px, per-thread sliding window.
// ---------------------------------------------------------------------------
__global__ __launch_bounds__(608) void k_hprod(const float* __restrict__ I,
                                               const float* __restrict__ p) {
    int by = blockIdx.x;
    int b = by / Hn, y = by % Hn;

    __shared__ float s[5][PADW];
    int tid = threadIdx.x;
    for (int i = tid; i < 5 * PADW; i += blockDim.x) {
        int pl = i / PADW, xx = (i % PADW) - POFF;
        float v = 0.f;
        if (xx >= 0 && xx < Wn) {
            v = (pl < 4) ? I[(((size_t)b * Cn + pl) * Hn + y) * Wn + xx]
                         : p[((size_t)b * Hn + y) * Wn + xx];
        }
        s[pl][i % PADW] = v;
    }
    __syncthreads();

    int ch  = tid >> 5;       // 0..18
    int seg = tid & 31;       // 0..31
    if (ch >= NCH) return;
    int a  = c_chA[ch];
    int bb = c_chB[ch];
    const float* sa = s[a];
    const float* sb = (bb >= 0) ? s[bb] : sa;   // warp-uniform
    bool mul = (bb >= 0);

    int x0 = seg * 24;
    float sum = 0.f;
#pragma unroll
    for (int k = -Rr; k <= Rr; k++) {
        int sx = x0 + k + POFF;
        float v = sa[sx];
        if (mul) v *= sb[sx];
        sum += v;
    }
    float* out = g_hsum + (((size_t)b * NCH + ch) * Hn + y) * Wn;
    out[x0] = sum;
#pragma unroll
    for (int j = 1; j < 24; j++) {
        int x = x0 + j;
        float vl = sa[x + Rr + POFF];
        float vt = sa[x - Rr - 1 + POFF];
        if (mul) { vl *= sb[x + Rr + POFF]; vt *= sb[x - Rr - 1 + POFF]; }
        sum += vl - vt;
        out[x] = sum;
    }
}

// ---------------------------------------------------------------------------
// K2: vertical box (column sliding, 19 running sums in regs) + per-pixel
// 4x4 SPD solve M x = 1 -> Asum, b.
// grid (3 x-strips of 256, 8 y-strips of 96, B)
// ---------------------------------------------------------------------------
__global__ __launch_bounds__(256) void k_vsolve() {
    int x  = blockIdx.x * 256 + threadIdx.x;
    int y0 = blockIdx.y * 96;
    int b  = blockIdx.z;

    const float* base = g_hsum + (size_t)b * NCH * Hn * Wn;
    float S[NCH];
#pragma unroll
    for (int c = 0; c < NCH; c++) S[c] = 0.f;

    for (int yy = y0 - Rr; yy <= y0 + Rr; yy++) {
        if (yy >= 0 && yy < Hn) {
#pragma unroll
            for (int c = 0; c < NCH; c++)
                S[c] += base[((size_t)c * Hn + yy) * Wn + x];
        }
    }

    int cntx = wcnt(x, Wn);
    for (int y = y0; y < y0 + 96; y++) {
        float invN = 1.0f / (float)(wcnt(y, Hn) * cntx);

        float m0 = S[0] * invN, m1 = S[1] * invN, m2 = S[2] * invN, m3 = S[3] * invN;
        float pm = S[4] * invN;
        float ip0 = S[5] * invN, ip1 = S[6] * invN, ip2 = S[7] * invN, ip3 = S[8] * invN;

        float Mm[4][4];
        Mm[0][0] = S[9]  * invN + EPSc;
        Mm[0][1] = Mm[1][0] = S[10] * invN;
        Mm[0][2] = Mm[2][0] = S[11] * invN;
        Mm[0][3] = Mm[3][0] = S[12] * invN;
        Mm[1][1] = S[13] * invN + EPSc;
        Mm[1][2] = Mm[2][1] = S[14] * invN;
        Mm[1][3] = Mm[3][1] = S[15] * invN;
        Mm[2][2] = S[16] * invN + EPSc;
        Mm[2][3] = Mm[3][2] = S[17] * invN;
        Mm[3][3] = S[18] * invN + EPSc;

        // Solve M xv = 1 (Gaussian elimination, SPD so no pivoting)
        float xv[4] = {1.f, 1.f, 1.f, 1.f};
#pragma unroll
        for (int k = 0; k < 4; k++) {
            float inv = 1.0f / Mm[k][k];
#pragma unroll
            for (int j = 0; j < 4; j++) if (j > k) Mm[k][j] *= inv;
            xv[k] *= inv;
#pragma unroll
            for (int i = 0; i < 4; i++) if (i > k) {
                float f = Mm[i][k];
#pragma unroll
                for (int j = 0; j < 4; j++) if (j > k) Mm[i][j] -= f * Mm[k][j];
                xv[i] -= f * xv[k];
            }
        }
#pragma unroll
        for (int k = 2; k >= 0; k--) {
#pragma unroll
            for (int j = 0; j < 4; j++) if (j > k) xv[k] -= Mm[k][j] * xv[j];
        }

        float ft0 = ip0 - pm * m0;
        float ft1 = ip1 - pm * m1;
        float ft2 = ip2 - pm * m2;
        float ft3 = ip3 - pm * m3;
        float Asum = ft0 * xv[0] + ft1 * xv[1] + ft2 * xv[2] + ft3 * xv[3];
        float msum = m0 + m1 + m2 + m3;
        float bv   = pm - Asum * msum;

        size_t pix = ((size_t)b * Hn + y) * Wn + x;
        g_Ab[pix] = Asum;
        g_Ab[(size_t)Bn * Hn * Wn + pix] = bv;

        int ylead = y + Rr + 1, ytrail = y - Rr;
        if (ylead < Hn) {
#pragma unroll
            for (int c = 0; c < NCH; c++)
                S[c] += base[((size_t)c * Hn + ylead) * Wn + x];
        }
        if (ytrail >= 0) {
#pragma unroll
            for (int c = 0; c < NCH; c++)
                S[c] -= base[((size_t)c * Hn + ytrail) * Wn + x];
        }
    }
}

// ---------------------------------------------------------------------------
// K3a: horizontal box of Asum, b. 256 threads = 2 ch x 128 segments of 6 px.
// ---------------------------------------------------------------------------
__global__ __launch_bounds__(256) void k_hAb() {
    int by = blockIdx.x;
    int b = by / Hn, y = by % Hn;

    __shared__ float s[2][PADW];
    int tid = threadIdx.x;
    for (int i = tid; i < 2 * PADW; i += blockDim.x) {
        int pl = i / PADW, xx = (i % PADW) - POFF;
        float v = 0.f;
        if (xx >= 0 && xx < Wn)
            v = g_Ab[(size_t)pl * Bn * Hn * Wn + ((size_t)b * Hn + y) * Wn + xx];
        s[pl][i % PADW] = v;
    }
    __syncthreads();

    int ch  = tid >> 7;      // 0..1
    int seg = tid & 127;     // 0..127
    const float* sa = s[ch];
    int x0 = seg * 6;
    float sum = 0.f;
#pragma unroll
    for (int k = -Rr; k <= Rr; k++) sum += sa[x0 + k + POFF];
    float* out = g_hAb + (size_t)ch * Bn * Hn * Wn + ((size_t)b * Hn + y) * Wn;
    out[x0] = sum;
#pragma unroll
    for (int j = 1; j < 6; j++) {
        int x = x0 + j;
        sum += sa[x + Rr + POFF] - sa[x - Rr - 1 + POFF];
        out[x] = sum;
    }
}

// ---------------------------------------------------------------------------
// K3b: vertical box of Asum,b + final combine:
//      q = (boxA/N) * sum_c I_c + boxb/N
// ---------------------------------------------------------------------------
__global__ __launch_bounds__(256) void k_final(const float* __restrict__ I,
                                               float* __restrict__ q) {
    int x  = blockIdx.x * 256 + threadIdx.x;
    int y0 = blockIdx.y * 96;
    int b  = blockIdx.z;

    const float* pA = g_hAb;
    const float* pB = g_hAb + (size_t)Bn * Hn * Wn;

    float SA = 0.f, SB = 0.f;
    for (int yy = y0 - Rr; yy <= y0 + Rr; yy++) {
        if (yy >= 0 && yy < Hn) {
            size_t idx = ((size_t)b * Hn + yy) * Wn + x;
            SA += pA[idx];
            SB += pB[idx];
        }
    }

    int cntx = wcnt(x, Wn);
    for (int y = y0; y < y0 + 96; y++) {
        float invN = 1.0f / (float)(wcnt(y, Hn) * cntx);
        size_t pix = ((size_t)b * Hn + y) * Wn + x;

        float isum = I[(((size_t)b * Cn + 0) * Hn + y) * Wn + x]
                   + I[(((size_t)b * Cn + 1) * Hn + y) * Wn + x]
                   + I[(((size_t)b * Cn + 2) * Hn + y) * Wn + x]
                   + I[(((size_t)b * Cn + 3) * Hn + y) * Wn + x];

        q[pix] = (SA * invN) * isum + (SB * invN);

        int ylead = y + Rr + 1, ytrail = y - Rr;
        if (ylead < Hn) {
            size_t idx = ((size_t)b * Hn + ylead) * Wn + x;
            SA += pA[idx]; SB += pB[idx];
        }
        if (ytrail >= 0) {
            size_t idx = ((size_t)b * Hn + ytrail) * Wn + x;
            SA -= pA[idx]; SB -= pB[idx];
        }
    }
}

extern "C" void kernel_launch(void* const* d_in, const int* in_sizes, int n_in,
                              void* d_out, int out_size) {
    const float* I = (const float*)d_in[0];
    const float* p = (const float*)d_in[1];
    float* q = (float*)d_out;

    k_hprod<<<Bn * Hn, 608>>>(I, p);
    k_vsolve<<<dim3(3, 8, Bn), 256>>>();
    k_hAb<<<Bn * Hn, 256>>>();
    k_final<<<dim3(3, 8, Bn), 256>>>(I, q);
}

// round 4
// speedup vs baseline: 1.5102x; 1.5102x over previous
#include <cuda_runtime.h>
#include <cstddef>

#define Bn 8
#define Cn 4
#define Hn 768
#define Wn 768
#define Rr 8
#define NCH 19
#define EPSc 1e-4f

// A-sum and b intermediate (only 2 channels survive stage 1)
__device__ float g_Ab[(size_t)2 * Bn * Hn * Wn];

// channel -> (planeA, planeB); plane 4 = p, 0..3 = I_c, B=-1 -> identity
__constant__ int c_chA[NCH] = {0,1,2,3, 4, 4,4,4,4, 0,0,0,0,1,1,1,2,2,3};
__constant__ int c_chB[NCH] = {-1,-1,-1,-1, -1, 0,1,2,3, 0,1,2,3,1,2,3,2,3,3};

__device__ __forceinline__ int wcnt(int t, int L) {
    int lo = t - Rr; if (lo < 0) lo = 0;
    int hi = t + Rr; if (hi > L - 1) hi = L - 1;
    return hi - lo + 1;
}

// ---------------------------------------------------------------------------
// Stage 1: fused products + 2D box (tile-local) + per-pixel 4x4 SPD solve.
// Tile 32x32, halo 8 -> extended 48x48. 512 threads.
// SMEM layout (floats):
//   hs  [0, 30096)              : 19 ch x 48 rows x 33 (pad)
//   raw [30096, 41856)          : 5 planes x 48 rows x 49 (pad)   (phase 0-1)
//   out [30096, 49552)          : 19 ch x 32 x 32                 (phase 2-3, aliases raw)
// ---------------------------------------------------------------------------
#define T1 32
#define E1 48
#define RP1 49
#define HP1 33
#define SZ_HS (NCH * E1 * HP1)     // 30096
#define SZ_OUT (NCH * T1 * T1)     // 19456
#define SMEM1_BYTES ((SZ_HS + SZ_OUT) * 4)   // 198208

__global__ __launch_bounds__(512) void k_stage1(const float* __restrict__ I,
                                                const float* __restrict__ p) {
    extern __shared__ float sm[];
    float* hs  = sm;
    float* raw = sm + SZ_HS;
    float* out = sm + SZ_HS;   // aliases raw (raw dead after phase 1)

    int b  = blockIdx.z;
    int X0 = blockIdx.x * T1, Y0 = blockIdx.y * T1;
    int tid = threadIdx.x;

    // ---- Phase 0: load raw halo tile (5 planes, zero-padded) ----
    for (int i = tid; i < 5 * E1 * E1; i += 512) {
        int pl = i / (E1 * E1);
        int r  = i % (E1 * E1);
        int ey = r / E1, ex = r % E1;
        int gy = Y0 - Rr + ey, gx = X0 - Rr + ex;
        float v = 0.f;
        if (gx >= 0 && gx < Wn && gy >= 0 && gy < Hn)
            v = (pl < 4) ? I[(((size_t)b * Cn + pl) * Hn + gy) * Wn + gx]
                         : p[((size_t)b * Hn + gy) * Wn + gx];
        raw[(pl * E1 + ey) * RP1 + ex] = v;
    }
    __syncthreads();

    // ---- Phase 1: horizontal 17-tap box of 19 product channels ----
    for (int t = tid; t < NCH * E1; t += 512) {
        int ey = t % E1, ch = t / E1;
        const float* ra = raw + (c_chA[ch] * E1 + ey) * RP1;
        int bb = c_chB[ch];
        const float* rb = (bb >= 0) ? raw + (bb * E1 + ey) * RP1 : ra;
        bool mul = (bb >= 0);
        float s = 0.f;
#pragma unroll
        for (int i = 0; i < 17; i++) {
            float v = ra[i];
            if (mul) v *= rb[i];
            s += v;
        }
        float* hrow = hs + (ch * E1 + ey) * HP1;
        hrow[0] = s;
#pragma unroll 4
        for (int x = 1; x < T1; x++) {
            float vl = ra[x + 16], vt = ra[x - 1];
            if (mul) { vl *= rb[x + 16]; vt *= rb[x - 1]; }
            s += vl - vt;
            hrow[x] = s;
        }
    }
    __syncthreads();

    // ---- Phase 2: vertical 17-tap box -> out (overwrites raw region) ----
    for (int t = tid; t < NCH * T1; t += 512) {
        int col = t & 31, ch = t >> 5;
        const float* h0 = hs + (size_t)ch * E1 * HP1 + col;
        float s = 0.f;
#pragma unroll
        for (int j = 0; j < 17; j++) s += h0[j * HP1];
        float* o = out + (ch * T1) * T1 + col;
        o[0] = s;
#pragma unroll 4
        for (int y = 1; y < T1; y++) {
            s += h0[(y + 16) * HP1] - h0[(y - 1) * HP1];
            o[y * T1] = s;
        }
    }
    __syncthreads();

    // ---- Phase 3: per-pixel 4x4 SPD solve  M x = 1 ----
    for (int k = tid; k < T1 * T1; k += 512) {
        int x = k & 31, y = k >> 5;
        float invN = 1.0f / (float)(wcnt(X0 + x, Wn) * wcnt(Y0 + y, Hn));

        float S[NCH];
#pragma unroll
        for (int c = 0; c < NCH; c++) S[c] = out[(c * T1 + y) * T1 + x];

        float m0 = S[0] * invN, m1 = S[1] * invN, m2 = S[2] * invN, m3 = S[3] * invN;
        float pm = S[4] * invN;
        float ip0 = S[5] * invN, ip1 = S[6] * invN, ip2 = S[7] * invN, ip3 = S[8] * invN;

        float Mm[4][4];
        Mm[0][0] = S[9]  * invN + EPSc;
        Mm[0][1] = Mm[1][0] = S[10] * invN;
        Mm[0][2] = Mm[2][0] = S[11] * invN;
        Mm[0][3] = Mm[3][0] = S[12] * invN;
        Mm[1][1] = S[13] * invN + EPSc;
        Mm[1][2] = Mm[2][1] = S[14] * invN;
        Mm[1][3] = Mm[3][1] = S[15] * invN;
        Mm[2][2] = S[16] * invN + EPSc;
        Mm[2][3] = Mm[3][2] = S[17] * invN;
        Mm[3][3] = S[18] * invN + EPSc;

        float xv[4] = {1.f, 1.f, 1.f, 1.f};
#pragma unroll
        for (int kk = 0; kk < 4; kk++) {
            float inv = 1.0f / Mm[kk][kk];
#pragma unroll
            for (int j = 0; j < 4; j++) if (j > kk) Mm[kk][j] *= inv;
            xv[kk] *= inv;
#pragma unroll
            for (int i = 0; i < 4; i++) if (i > kk) {
                float f = Mm[i][kk];
#pragma unroll
                for (int j = 0; j < 4; j++) if (j > kk) Mm[i][j] -= f * Mm[kk][j];
                xv[i] -= f * xv[kk];
            }
        }
#pragma unroll
        for (int kk = 2; kk >= 0; kk--) {
#pragma unroll
            for (int j = 0; j < 4; j++) if (j > kk) xv[kk] -= Mm[kk][j] * xv[j];
        }

        float ft0 = ip0 - pm * m0;
        float ft1 = ip1 - pm * m1;
        float ft2 = ip2 - pm * m2;
        float ft3 = ip3 - pm * m3;
        float Asum = ft0 * xv[0] + ft1 * xv[1] + ft2 * xv[2] + ft3 * xv[3];
        float msum = m0 + m1 + m2 + m3;
        float bv   = pm - Asum * msum;

        size_t pix = ((size_t)b * Hn + (Y0 + y)) * Wn + (X0 + x);
        g_Ab[pix] = Asum;
        g_Ab[(size_t)Bn * Hn * Wn + pix] = bv;
    }
}

// ---------------------------------------------------------------------------
// Stage 2: fused 2D box of (Asum, b) + final combine.
// Tile 64x64, halo 8 -> extended 80x80. 512 threads.
// SMEM (floats): rawAB 2x80x81 = 12960 ; hsAB 2x80x65 = 10400  -> 93440 B
// Vertical pass fused with combine: thread = (column, y-segment), running sums.
// ---------------------------------------------------------------------------
#define T2 64
#define E2 80
#define RP2 81
#define HP2 65
#define SZ2_RAW (2 * E2 * RP2)   // 12960
#define SZ2_HS  (2 * E2 * HP2)   // 10400
#define SMEM2_BYTES ((SZ2_RAW + SZ2_HS) * 4)   // 93440
#define YSEG 8                    // 64 cols x 8 segs = 512 threads, 8 rows each

__global__ __launch_bounds__(512) void k_stage2(const float* __restrict__ I,
                                                float* __restrict__ q) {
    extern __shared__ float sm[];
    float* raw = sm;
    float* hsb = sm + SZ2_RAW;

    int b  = blockIdx.z;
    int X0 = blockIdx.x * T2, Y0 = blockIdx.y * T2;
    int tid = threadIdx.x;
    const size_t PL = (size_t)Bn * Hn * Wn;

    // ---- Phase 0: load A,b halo tiles ----
    for (int i = tid; i < 2 * E2 * E2; i += 512) {
        int pl = i / (E2 * E2);
        int r  = i % (E2 * E2);
        int ey = r / E2, ex = r % E2;
        int gy = Y0 - Rr + ey, gx = X0 - Rr + ex;
        float v = 0.f;
        if (gx >= 0 && gx < Wn && gy >= 0 && gy < Hn)
            v = g_Ab[(size_t)pl * PL + ((size_t)b * Hn + gy) * Wn + gx];
        raw[(pl * E2 + ey) * RP2 + ex] = v;
    }
    __syncthreads();

    // ---- Phase 1: horizontal box (2 ch x 80 rows = 160 tasks) ----
    for (int t = tid; t < 2 * E2; t += 512) {
        int ey = t % E2, ch = t / E2;
        const float* ra = raw + (ch * E2 + ey) * RP2;
        float s = 0.f;
#pragma unroll
        for (int i = 0; i < 17; i++) s += ra[i];
        float* hrow = hsb + (ch * E2 + ey) * HP2;
        hrow[0] = s;
#pragma unroll 4
        for (int x = 1; x < T2; x++) {
            s += ra[x + 16] - ra[x - 1];
            hrow[x] = s;
        }
    }
    __syncthreads();

    // ---- Phase 2: vertical box + combine, thread = (col, y-segment) ----
    {
        int col = tid & 63;
        int seg = tid >> 6;          // 0..7
        int ys  = seg * YSEG;        // local y start
        const float* hA = hsb + col;
        const float* hB = hsb + (size_t)E2 * HP2 + col;

        float SA = 0.f, SB = 0.f;
#pragma unroll
        for (int j = 0; j < 17; j++) {
            SA += hA[(ys + j) * HP2];
            SB += hB[(ys + j) * HP2];
        }
        int gx = X0 + col;
        int cntx = wcnt(gx, Wn);
        const float* Ib = I + ((size_t)b * Cn) * Hn * Wn;

#pragma unroll
        for (int yy = 0; yy < YSEG; yy++) {
            int gy = Y0 + ys + yy;
            float invN = 1.0f / (float)(wcnt(gy, Hn) * cntx);
            size_t row = (size_t)gy * Wn + gx;
            float isum = Ib[row]
                       + Ib[(size_t)Hn * Wn + row]
                       + Ib[(size_t)2 * Hn * Wn + row]
                       + Ib[(size_t)3 * Hn * Wn + row];
            q[((size_t)b * Hn + gy) * Wn + gx] = (SA * invN) * isum + SB * invN;

            if (yy < YSEG - 1) {
                int lead = ys + yy + 17, trail = ys + yy;
                SA += hA[lead * HP2] - hA[trail * HP2];
                SB += hB[lead * HP2] - hB[trail * HP2];
            }
        }
    }
}

extern "C" void kernel_launch(void* const* d_in, const int* in_sizes, int n_in,
                              void* d_out, int out_size) {
    const float* I = (const float*)d_in[0];
    const float* p = (const float*)d_in[1];
    float* q = (float*)d_out;

    static bool attr_done = false;
    if (!attr_done) {
        cudaFuncSetAttribute(k_stage1, cudaFuncAttributeMaxDynamicSharedMemorySize, SMEM1_BYTES);
        cudaFuncSetAttribute(k_stage2, cudaFuncAttributeMaxDynamicSharedMemorySize, SMEM2_BYTES);
        attr_done = true;
    }

    k_stage1<<<dim3(Wn / T1, Hn / T1, Bn), 512, SMEM1_BYTES>>>(I, p);
    k_stage2<<<dim3(Wn / T2, Hn / T2, Bn), 512, SMEM2_BYTES>>>(I, q);
}